// round 15
// baseline (speedup 1.0000x reference)
#include <cuda_runtime.h>
#include <cuda_fp16.h>
#include <cstdint>

#define IN_DIM  2048
#define HDIM    8192
#define OUT_DIM 512
#define NBATCH  4096

typedef __half fp16;

// ---------------- scratch (static __device__ per harness rules) ----------------
__device__ __align__(256) fp16 g_xhi [(size_t)NBATCH * IN_DIM];
__device__ __align__(256) fp16 g_xlo [(size_t)NBATCH * IN_DIM];
__device__ __align__(256) int8_t g_xloq[(size_t)NBATCH * IN_DIM];
__device__ __align__(256) fp16 g_W1hi[(size_t)IN_DIM * HDIM];     // Ŵ1 = W1/s1
__device__ __align__(256) fp16 g_W1Thi[(size_t)HDIM * IN_DIM];
__device__ __align__(256) int8_t g_W1Tq[(size_t)HDIM * IN_DIM];
__device__ __align__(256) fp16 g_W2Thi[(size_t)OUT_DIM * HDIM];   // Ŵ2ᵀ = (W2/s2)ᵀ
__device__ __align__(256) fp16 g_z1hi[(size_t)NBATCH * HDIM];
__device__ __align__(256) fp16 g_zhi [(size_t)NBATCH * OUT_DIM];
__device__ __align__(256) fp16 g_zlo [(size_t)NBATCH * OUT_DIM];
__device__ __align__(256) float g_part[(size_t)4 * IN_DIM * OUT_DIM]; // GM K-split partials
__device__ __align__(256) fp16 g_Mhi [(size_t)IN_DIM * OUT_DIM];  // M̂ = Ŵ1@Ŵ2
__device__ __align__(256) float g_dvec[IN_DIM];                   // db1@W1ᵀ + db2
__device__ int g_maskmode;
__device__ unsigned g_xsbits;   // max|xlo| bits
__device__ unsigned g_wsbits;   // max|Ŵ1T| bits

// ---------------- PTX helpers (compute_100-safe) ----------------
__device__ __forceinline__ uint32_t smem_u32(const void* p) {
    uint32_t a;
    asm("{ .reg .u64 t; cvta.to.shared.u64 t, %1; cvt.u32.u64 %0, t; }" : "=r"(a) : "l"(p));
    return a;
}
#define SWZ128(off) ((off) ^ (((off) >> 3) & 0x70))

__device__ __forceinline__ void cp16cp(uint32_t dst, const void* src) {
    asm volatile("cp.async.cg.shared.global [%0], [%1], 16;" :: "r"(dst), "l"(src));
}
#define CP_COMMIT() asm volatile("cp.async.commit_group;" ::: "memory")
#define CP_WAIT(n)  asm volatile("cp.async.wait_group %0;" :: "n"(n) : "memory")

__device__ __forceinline__ void ldsm4(uint32_t a, uint32_t& r0, uint32_t& r1,
                                      uint32_t& r2, uint32_t& r3) {
    asm volatile("ldmatrix.sync.aligned.m8n8.x4.shared.b16 {%0,%1,%2,%3}, [%4];"
                 : "=r"(r0), "=r"(r1), "=r"(r2), "=r"(r3) : "r"(a));
}

__device__ __forceinline__ void mma16816(float* d, const uint32_t* a, const uint32_t* b) {
    asm volatile("mma.sync.aligned.m16n8k16.row.col.f32.f16.f16.f32 "
        "{%0,%1,%2,%3}, {%4,%5,%6,%7}, {%8,%9}, {%0,%1,%2,%3};"
        : "+f"(d[0]), "+f"(d[1]), "+f"(d[2]), "+f"(d[3])
        : "r"(a[0]), "r"(a[1]), "r"(a[2]), "r"(a[3]), "r"(b[0]), "r"(b[1]));
}

__device__ __forceinline__ void imma16832(int* d, const uint32_t* a, const uint32_t* b) {
    asm volatile("mma.sync.aligned.m16n8k32.row.col.s32.s8.s8.s32 "
        "{%0,%1,%2,%3}, {%4,%5,%6,%7}, {%8,%9}, {%0,%1,%2,%3};"
        : "+r"(d[0]), "+r"(d[1]), "+r"(d[2]), "+r"(d[3])
        : "r"(a[0]), "r"(a[1]), "r"(a[2]), "r"(a[3]), "r"(b[0]), "r"(b[1]));
}

// ---------------- mask dtype detection + scale init ----------------
__global__ void detect_mask_kernel(const unsigned int* __restrict__ m, int nwords) {
    __shared__ int ok[4];
    if (threadIdx.x < 4) ok[threadIdx.x] = 1;
    __syncthreads();
    for (int i = threadIdx.x; i < nwords; i += blockDim.x) {
        unsigned w = m[i];
        if (!(w == 0u || w == 1u))          atomicAnd(&ok[0], 0);
        if (!(w == 0u || w == 0x3F800000u)) atomicAnd(&ok[1], 0);
        unsigned lo = w & 0xFFFFu, hi = w >> 16;
        if (!((lo == 0u || lo == 0x3F80u) && (hi == 0u || hi == 0x3F80u))) atomicAnd(&ok[2], 0);
        if (!((lo == 0u || lo == 0x3C00u) && (hi == 0u || hi == 0x3C00u))) atomicAnd(&ok[3], 0);
    }
    __syncthreads();
    if (threadIdx.x == 0) {
        int mode = 0;
        if      (ok[0]) mode = 1;
        else if (ok[1]) mode = 2;
        else if (ok[2]) mode = 3;
        else if (ok[3]) mode = 4;
        g_maskmode = mode;
        g_xsbits = 0u;
        g_wsbits = 0u;
    }
}

__device__ __forceinline__ int read_mask(const void* p, long i, int mode) {
    switch (mode) {
        case 1:  return ((const int*)p)[i] != 0;
        case 2:  return ((const float*)p)[i] != 0.0f;
        case 3:  return ((const unsigned short*)p)[i] != 0;
        case 4:  return ((const unsigned short*)p)[i] != 0;
        default: return ((const unsigned char*)p)[i] != 0;
    }
}

__device__ __forceinline__ void split2h(float v, fp16& h, fp16& l) {
    h = __float2half(v);
    l = __float2half(v - __half2float(h));
}

__device__ __forceinline__ void warp_amax_atomic(float m, unsigned* dst) {
#pragma unroll
    for (int o = 16; o; o >>= 1)
        m = fmaxf(m, __shfl_xor_sync(0xFFFFFFFFu, m, o));
    if ((threadIdx.x & 31) == 0) atomicMax(dst, __float_as_uint(m));
}

// ---------------- fused prepass: split x | dequant W1 | dequant W2 ----------
#define NB_SPLIT (NBATCH * IN_DIM / 4 / 256)      // 8192
#define NB_DQ1   ((HDIM / 32) * (IN_DIM / 32))    // 16384
#define NB_DQ2   ((OUT_DIM / 32) * (HDIM / 32))   // 4096

__device__ __forceinline__ void dequant_block(
    const int* __restrict__ idx, const void* __restrict__ mask,
    const float* __restrict__ wf, const float* __restrict__ cb,
    fp16* __restrict__ Whi, fp16* __restrict__ WThi,
    int R, int C, int bx, int by, float tile[32][33], int track_max) {
    const int mode = g_maskmode;
    float s = __ldg(cb + 3);
    if (s == 0.0f) s = 1.0f;
    const int c0 = bx * 32;
    const int r0 = by * 32;
    const int tx = threadIdx.x & 31;
    const int ty = threadIdx.x >> 5;      // 0..7
    float amax = 0.0f;
    for (int rr = ty; rr < 32; rr += 8) {
        long off = (long)(r0 + rr) * C + c0 + tx;
        int  m = read_mask(mask, off, mode);
        float v = (m ? cb[idx[off]] : wf[off]) / s;   // exact for codebook
        if (Whi) Whi[off] = __float2half(v);
        amax = fmaxf(amax, fabsf(v));
        tile[rr][tx] = v;
    }
    if (track_max) warp_amax_atomic(amax, &g_wsbits);
    __syncthreads();
    for (int rr = ty; rr < 32; rr += 8) {
        float v = tile[tx][rr];
        long off = (long)(c0 + rr) * R + r0 + tx;
        WThi[off] = __float2half(v);
    }
}

__global__ void prepass_kernel(
    const float4* __restrict__ x4, fp16* __restrict__ xhi, fp16* __restrict__ xlo,
    const int* __restrict__ W1i, const void* __restrict__ W1m,
    const float* __restrict__ W1f, const float* __restrict__ cb1,
    fp16* __restrict__ W1hi, fp16* __restrict__ W1Thi,
    const int* __restrict__ W2i, const void* __restrict__ W2m,
    const float* __restrict__ W2f, const float* __restrict__ cb2,
    fp16* __restrict__ W2Thi) {
    __shared__ float tile[32][33];
    const int b = blockIdx.x;
    if (b < NB_SPLIT) {
        size_t i = (size_t)b * 256 + threadIdx.x;
        float4 v = x4[i];
        fp16 h0, l0, h1, l1, h2, l2, h3, l3;
        split2h(v.x, h0, l0); split2h(v.y, h1, l1);
        split2h(v.z, h2, l2); split2h(v.w, h3, l3);
        ((__half2*)xhi)[2 * i]     = __halves2half2(h0, h1);
        ((__half2*)xhi)[2 * i + 1] = __halves2half2(h2, h3);
        ((__half2*)xlo)[2 * i]     = __halves2half2(l0, l1);
        ((__half2*)xlo)[2 * i + 1] = __halves2half2(l2, l3);
        float am = fmaxf(fmaxf(fabsf(__half2float(l0)), fabsf(__half2float(l1))),
                         fmaxf(fabsf(__half2float(l2)), fabsf(__half2float(l3))));
        warp_amax_atomic(am, &g_xsbits);
    } else if (b < NB_SPLIT + NB_DQ1) {
        int j = b - NB_SPLIT;
        dequant_block(W1i, W1m, W1f, cb1, W1hi, W1Thi,
                      IN_DIM, HDIM, j & 255, j >> 8, tile, 1);
    } else {
        int j = b - NB_SPLIT - NB_DQ1;
        dequant_block(W2i, W2m, W2f, cb2, nullptr, W2Thi,
                      HDIM, OUT_DIM, j & 15, j >> 4, tile, 0);
    }
}

// ---------------- quantize xlo and W1Thi to int8 (per-tensor scales) --------
#define NB_QX ((NBATCH * IN_DIM) / 1024)          // 8192
#define NB_QW ((HDIM * IN_DIM) / 1024)            // 16384

__device__ __forceinline__ int8_t q8(fp16 h, float sc) {
    int r = __float2int_rn(__half2float(h) * sc);
    r = max(-127, min(127, r));
    return (int8_t)r;
}

__global__ void quant_kernel(const fp16* __restrict__ xlo, int8_t* __restrict__ xloq,
                             const fp16* __restrict__ W1Thi, int8_t* __restrict__ W1Tq) {
    const int b = blockIdx.x;
    const fp16* src;
    int8_t* dst;
    float sc;
    size_t i;
    if (b < NB_QX) {
        float xs = __uint_as_float(g_xsbits);
        sc = xs > 0.0f ? 127.0f / xs : 0.0f;
        i = (size_t)b * 1024 + threadIdx.x * 4;
        src = xlo; dst = xloq;
    } else {
        float ws = __uint_as_float(g_wsbits);
        sc = ws > 0.0f ? 127.0f / ws : 0.0f;
        i = (size_t)(b - NB_QX) * 1024 + threadIdx.x * 4;
        src = W1Thi; dst = W1Tq;
    }
    __half2 p0 = *(const __half2*)(src + i);
    __half2 p1 = *(const __half2*)(src + i + 2);
    char4 q;
    q.x = q8(__low2half(p0),  sc);
    q.y = q8(__high2half(p0), sc);
    q.z = q8(__low2half(p1),  sc);
    q.w = q8(__high2half(p1), sc);
    *(char4*)(dst + i) = q;
}

// ---------------- fused post-GM: reduce M partials | dvec ----------------
#define NB_RM ((IN_DIM * OUT_DIM) / 256)          // 4096

__global__ void postgm_kernel(const float* __restrict__ part,
                              fp16* __restrict__ Mhi,
                              const fp16* __restrict__ W1hi,
                              const float* __restrict__ db1, const float* __restrict__ db2,
                              const float* __restrict__ cb1, float* __restrict__ dvec) {
    __shared__ float red[256];
    const int b = blockIdx.x;
    if (b < NB_RM) {
        size_t i = (size_t)b * 256 + threadIdx.x;
        const size_t n = (size_t)IN_DIM * OUT_DIM;
        float v = part[i] + part[i + n] + part[i + 2 * n] + part[i + 3 * n];
        Mhi[i] = __float2half(v);
    } else {
        const int j = b - NB_RM;
        float s = __ldg(cb1 + 3);
        if (s == 0.0f) s = 1.0f;
        float sum = 0.0f;
        const size_t base = (size_t)j * HDIM;
        for (int h = threadIdx.x; h < HDIM; h += 256)
            sum += __half2float(W1hi[base + h]) * __ldg(db1 + h);
        red[threadIdx.x] = sum;
        __syncthreads();
        for (int st = 128; st > 0; st >>= 1) {
            if (threadIdx.x < st) red[threadIdx.x] += red[threadIdx.x + st];
            __syncthreads();
        }
        if (threadIdx.x == 0) dvec[j] = fmaf(s, red[0], __ldg(db2 + j));
    }
}

// ---------------- c19 activation ----------------
__device__ __forceinline__ float c19f(float x, float craw, float rhoraw) {
    float c   = fmaxf(craw, 0.1f);
    float rho = fmaxf(rhoraw, 0.0f);
    float L   = 6.0f * c;
    float s   = x / c;
    float n   = floorf(s);
    float t   = s - n;
    float h   = t * (1.0f - t);
    float sgn = (fmodf(n, 2.0f) == 0.0f) ? 1.0f : -1.0f;
    float interior = c * (sgn * h + rho * h * h);
    return (x >= L) ? (x - L) : ((x <= -L) ? (x + L) : interior);
}

// ---------------- specialized G1: int8 correction + fp16 main ----------------
// z1 = c19(s1*(xhi@Ŵ1T + xlo@Ŵ1T) + b1); xlo@Ŵ1T done in int8 (per-tensor scales).
// Block 128x256, 8 warps 2x4 (warp 64x64). Phase1: s8 BK=64, 3 stages.
// Phase2: f16 BK=32, 4 stages. Shared 128-reg accumulator (int32 -> fp32 in place).
#define G1_AB (128 * 64)
#define G1_BB (256 * 64)
#define G1_ST (G1_AB + G1_BB)
#define SMEM_G1 (1024 + 4 * G1_ST)

__global__ void __launch_bounds__(256, 1)
g1_kernel(const fp16* __restrict__ xhi, const int8_t* __restrict__ xloq,
          const fp16* __restrict__ W1Thi, const int8_t* __restrict__ W1Tq,
          const float* __restrict__ cb1, const float* __restrict__ b1,
          const float* __restrict__ craw, const float* __restrict__ rho,
          fp16* __restrict__ z1hi) {
    extern __shared__ char smem[];
    const uint32_t sbase = smem_u32(smem);
    const uint32_t tbase = (sbase + 1023u) & ~1023u;
    const int tid  = threadIdx.x;
    const int wid  = tid >> 5;
    const int lane = tid & 31;
    const int wm = wid & 1;
    const int wn = wid >> 1;
    const int m0 = blockIdx.y * 128;
    const int n0 = blockIdx.x * 256;

    float sa = __ldg(cb1 + 3);
    if (sa == 0.0f) sa = 1.0f;

    float acc[4][8][4];
#pragma unroll
    for (int i = 0; i < 4; i++)
#pragma unroll
        for (int j = 0; j < 8; j++)
#pragma unroll
            for (int r = 0; r < 4; r++) acc[i][j][r] = 0.0f;   // int 0 == 0.0f bits

    // ================= phase 1: int8 correction (BK=64, 3 stages) =============
    {
        uint32_t sA[3], sB[3];
#pragma unroll
        for (int s = 0; s < 3; s++) { sA[s] = tbase + s * G1_ST; sB[s] = sA[s] + G1_AB; }
        auto fill = [&](int kc) {
            const int s = kc % 3;
            const size_t k0 = (size_t)kc * 64;
#pragma unroll
            for (int i = 0; i < 2; i++) {
                int ch = tid + i * 256, r = ch >> 2, c = ch & 3;
                cp16cp(sA[s] + SWZ128(r * 64 + c * 16),
                       xloq + (size_t)(m0 + r) * IN_DIM + k0 + c * 16);
            }
#pragma unroll
            for (int i = 0; i < 4; i++) {
                int ch = tid + i * 256, r = ch >> 2, c = ch & 3;
                cp16cp(sB[s] + SWZ128(r * 64 + c * 16),
                       W1Tq + (size_t)(n0 + r) * IN_DIM + k0 + c * 16);
            }
        };
        for (int it = 0; it < 2; it++) { fill(it); CP_COMMIT(); }
        const int IT = IN_DIM / 64;    // 32
        for (int it = 0; it < IT; it++) {
            CP_WAIT(1);
            __syncthreads();
            if (it + 2 < IT) fill(it + 2);
            CP_COMMIT();
            const int s = it % 3;
            const uint32_t Ab = sA[s], Bb = sB[s];
#pragma unroll
            for (int kk = 0; kk < 2; kk++) {     // two k32 IMMA steps per 64B row
                uint32_t af[4][4];
#pragma unroll
                for (int mi = 0; mi < 4; mi++) {
                    int row = wm * 64 + mi * 16 + (lane & 15);
                    int ch  = kk * 2 + (lane >> 4);
                    ldsm4(Ab + SWZ128(row * 64 + ch * 16),
                          af[mi][0], af[mi][1], af[mi][2], af[mi][3]);
                }
                uint32_t bf[8][2];
#pragma unroll
                for (int p = 0; p < 4; p++) {
                    int g   = lane >> 3;
                    int row = wn * 64 + (p * 2 + (g >> 1)) * 8 + (lane & 7);
                    int ch  = kk * 2 + (g & 1);
                    uint32_t r0, r1, r2, r3;
                    ldsm4(Bb + SWZ128(row * 64 + ch * 16), r0, r1, r2, r3);
                    bf[p * 2][0] = r0;  bf[p * 2][1] = r1;
                    bf[p * 2 + 1][0] = r2; bf[p * 2 + 1][1] = r3;
                }
#pragma unroll
                for (int mi = 0; mi < 4; mi++)
#pragma unroll
                    for (int ni = 0; ni < 8; ni++)
                        imma16832((int*)acc[mi][ni], af[mi], bf[ni]);
            }
        }
        CP_WAIT(0);
        __syncthreads();
    }

    // ---- convert int32 accumulators -> scaled fp32 (in place) ----
    {
        const float xs = __uint_as_float(g_xsbits);
        const float ws = __uint_as_float(g_wsbits);
        const float qs = (xs / 127.0f) * (ws / 127.0f);
        float* af = &acc[0][0][0];
#pragma unroll
        for (int i = 0; i < 128; i++) {
            int v = __float_as_int(af[i]);
            af[i] = qs * (float)v;
        }
    }

    // ================= phase 2: fp16 main product (BK=32, 4 stages) ===========
    {
        uint32_t sA[4], sB[4];
#pragma unroll
        for (int s = 0; s < 4; s++) { sA[s] = tbase + s * G1_ST; sB[s] = sA[s] + G1_AB; }
        auto fill = [&](int kc) {
            const int s = kc % 4;
            const size_t k0 = (size_t)kc * 32;
#pragma unroll
            for (int i = 0; i < 2; i++) {
                int ch = tid + i * 256, r = ch >> 2, c = ch & 3;
                cp16cp(sA[s] + SWZ128(r * 64 + c * 16),
                       (const char*)(xhi + (size_t)(m0 + r) * IN_DIM + k0) + c * 16);
            }
#pragma unroll
            for (int i = 0; i < 4; i++) {
                int ch = tid + i * 256, r = ch >> 2, c = ch & 3;
                cp16cp(sB[s] + SWZ128(r * 64 + c * 16),
                       (const char*)(W1Thi + (size_t)(n0 + r) * IN_DIM + k0) + c * 16);
            }
        };
        for (int it = 0; it < 3; it++) { fill(it); CP_COMMIT(); }
        const int IT = IN_DIM / 32;    // 64
        for (int it = 0; it < IT; it++) {
            CP_WAIT(2);
            __syncthreads();
            if (it + 3 < IT) fill(it + 3);
            CP_COMMIT();
            const int s = it % 4;
            const uint32_t Ab = sA[s], Bb = sB[s];
#pragma unroll
            for (int kk = 0; kk < 2; kk++) {
                uint32_t af[4][4];
#pragma unroll
                for (int mi = 0; mi < 4; mi++) {
                    int row = wm * 64 + mi * 16 + (lane & 15);
                    int ch  = kk * 2 + (lane >> 4);
                    ldsm4(Ab + SWZ128(row * 64 + ch * 16),
                          af[mi][0], af[mi][1], af[mi][2], af[mi][3]);
                }
                uint32_t bf[8][2];
#pragma unroll
                for (int p = 0; p < 4; p++) {
                    int g   = lane >> 3;
                    int row = wn * 64 + (p * 2 + (g >> 1)) * 8 + (lane & 7);
                    int ch  = kk * 2 + (g & 1);
                    uint32_t r0, r1, r2, r3;
                    ldsm4(Bb + SWZ128(row * 64 + ch * 16), r0, r1, r2, r3);
                    bf[p * 2][0] = r0;  bf[p * 2][1] = r1;
                    bf[p * 2 + 1][0] = r2; bf[p * 2 + 1][1] = r3;
                }
#pragma unroll
                for (int mi = 0; mi < 4; mi++)
#pragma unroll
                    for (int ni = 0; ni < 8; ni++)
                        mma16816(acc[mi][ni], af[mi], bf[ni]);
            }
        }
    }

    // ---------------- epilogue: s1*acc + b1 -> c19 -> z1hi ----------------
#pragma unroll
    for (int ni = 0; ni < 8; ni++) {
        const int n = n0 + wn * 64 + ni * 8 + 2 * (lane & 3);
        const float bv0 = __ldg(b1 + n), bv1 = __ldg(b1 + n + 1);
        const float c0 = __ldg(craw + n), c1 = __ldg(craw + n + 1);
        const float r0 = __ldg(rho + n),  r1 = __ldg(rho + n + 1);
#pragma unroll
        for (int mi = 0; mi < 4; mi++) {
#pragma unroll
            for (int h = 0; h < 2; h++) {
                const int m = m0 + wm * 64 + mi * 16 + (lane >> 2) + h * 8;
                float v0 = fmaf(sa, acc[mi][ni][2 * h],     bv0);
                float v1 = fmaf(sa, acc[mi][ni][2 * h + 1], bv1);
                v0 = c19f(v0, c0, r0);
                v1 = c19f(v1, c1, r1);
                *(__half2*)(z1hi + (size_t)m * HDIM + n) =
                    __halves2half2(__float2half(v0), __float2half(v1));
            }
        }
    }
}

// ---------------- generic fp16 multi-product GEMM (GM, G2, G5) ----------------
#define BM 128
#define BKK 32

template<int NI, int PA, int PB, int NSTAGE>
__global__ void __launch_bounds__(256, 1)
gemm_fp16_kernel(const fp16* __restrict__ Ahi, const fp16* __restrict__ Alo,
                 const fp16* __restrict__ Bhi, const fp16* __restrict__ Blo,
                 int M, int Nn, int Klen, int ldk,
                 const float* __restrict__ cba, const float* __restrict__ cbb,
                 const float* __restrict__ bias, int epi,
                 const float* __restrict__ craw, const float* __restrict__ rho,
                 float* __restrict__ Cf, fp16* __restrict__ Chi, fp16* __restrict__ Clo) {
    constexpr int BN = NI * 32;
    constexpr int A_BYTES = BM * 64;
    constexpr int B_BYTES = BN * 64;
    constexpr int STAGE_BYTES = PA * A_BYTES + PB * B_BYTES;
    extern __shared__ char smem[];
    const uint32_t sbase = smem_u32(smem);
    const uint32_t tbase = (sbase + 1023u) & ~1023u;
    const int tid  = threadIdx.x;
    const int wid  = tid >> 5;
    const int lane = tid & 31;
    const int wm = wid & 1;
    const int wn = wid >> 1;

    const int m0 = blockIdx.y * BM;
    const int n0 = blockIdx.x * BN;
    const size_t kbase = (size_t)blockIdx.z * Klen;

    float sa = cba ? __ldg(cba + 3) : 1.0f;  if (sa == 0.0f) sa = 1.0f;
    float sb = cbb ? __ldg(cbb + 3) : 1.0f;  if (sb == 0.0f) sb = 1.0f;
    const float sc = sa * sb;

    uint32_t sAh[NSTAGE], sAl[NSTAGE], sBh[NSTAGE], sBl[NSTAGE];
#pragma unroll
    for (int s = 0; s < NSTAGE; s++) {
        uint32_t b = tbase + s * STAGE_BYTES;
        sAh[s] = b;
        sAl[s] = b + A_BYTES;
        sBh[s] = b + PA * A_BYTES;
        sBl[s] = b + PA * A_BYTES + B_BYTES;
    }

    const int ITERS = Klen / BKK;

    float acc[4][NI][4];
#pragma unroll
    for (int i = 0; i < 4; i++)
#pragma unroll
        for (int j = 0; j < NI; j++)
#pragma unroll
            for (int r = 0; r < 4; r++) acc[i][j][r] = 0.0f;

    auto fill = [&](int kc) {
        const int s = kc % NSTAGE;
        const size_t k0 = kbase + (size_t)kc * BKK;
#pragma unroll
        for (int i = 0; i < 2; i++) {
            int ch = tid + i * 256;
            int r = ch >> 2, c = ch & 3;
            uint32_t so = SWZ128(r * 64 + c * 16);
            const char* pA = (const char*)(Ahi + (size_t)(m0 + r) * ldk + k0) + c * 16;
            cp16cp(sAh[s] + so, pA);
            if (PA == 2) {
                const char* pL = (const char*)(Alo + (size_t)(m0 + r) * ldk + k0) + c * 16;
                cp16cp(sAl[s] + so, pL);
            }
        }
#pragma unroll
        for (int i = 0; i < NI / 2; i++) {
            int ch = tid + i * 256;
            int r = ch >> 2, c = ch & 3;
            uint32_t so = SWZ128(r * 64 + c * 16);
            const char* pB = (const char*)(Bhi + (size_t)(n0 + r) * ldk + k0) + c * 16;
            cp16cp(sBh[s] + so, pB);
            if (PB == 2) {
                const char* pBl = (const char*)(Blo + (size_t)(n0 + r) * ldk + k0) + c * 16;
                cp16cp(sBl[s] + so, pBl);
            }
        }
    };

    for (int it = 0; it < NSTAGE - 1; it++) { fill(it); CP_COMMIT(); }

    for (int it = 0; it < ITERS; it++) {
        CP_WAIT(NSTAGE - 2);
        __syncthreads();
        if (it + NSTAGE - 1 < ITERS) fill(it + NSTAGE - 1);
        CP_COMMIT();

        const int s = it % NSTAGE;
#pragma unroll
        for (int kk = 0; kk < 2; kk++) {
            uint32_t afh[4][4], afl[4][4];
#pragma unroll
            for (int mi = 0; mi < 4; mi++) {
                int row = wm * 64 + mi * 16 + (lane & 15);
                int ch  = kk * 2 + (lane >> 4);
                uint32_t so = SWZ128(row * 64 + ch * 16);
                ldsm4(sAh[s] + so, afh[mi][0], afh[mi][1], afh[mi][2], afh[mi][3]);
                if (PA == 2)
                    ldsm4(sAl[s] + so, afl[mi][0], afl[mi][1], afl[mi][2], afl[mi][3]);
            }
            uint32_t bfh[NI][2], bfl[NI][2];
#pragma unroll
            for (int p = 0; p < NI / 2; p++) {
                int g   = lane >> 3;
                int row = wn * (NI * 8) + (p * 2 + (g >> 1)) * 8 + (lane & 7);
                int ch  = kk * 2 + (g & 1);
                uint32_t so = SWZ128(row * 64 + ch * 16);
                uint32_t r0, r1, r2, r3;
                ldsm4(sBh[s] + so, r0, r1, r2, r3);
                bfh[p * 2][0] = r0;  bfh[p * 2][1] = r1;
                bfh[p * 2 + 1][0] = r2; bfh[p * 2 + 1][1] = r3;
                if (PB == 2) {
                    ldsm4(sBl[s] + so, r0, r1, r2, r3);
                    bfl[p * 2][0] = r0;  bfl[p * 2][1] = r1;
                    bfl[p * 2 + 1][0] = r2; bfl[p * 2 + 1][1] = r3;
                }
            }
#pragma unroll
            for (int mi = 0; mi < 4; mi++)
#pragma unroll
                for (int ni = 0; ni < NI; ni++)
                    mma16816(acc[mi][ni], afh[mi], bfh[ni]);
            if (PA == 2) {
#pragma unroll
                for (int mi = 0; mi < 4; mi++)
#pragma unroll
                    for (int ni = 0; ni < NI; ni++)
                        mma16816(acc[mi][ni], afl[mi], bfh[ni]);
            }
            if (PB == 2) {
#pragma unroll
                for (int mi = 0; mi < 4; mi++)
#pragma unroll
                    for (int ni = 0; ni < NI; ni++)
                        mma16816(acc[mi][ni], afh[mi], bfl[ni]);
            }
        }
    }

    float* CfZ = Cf ? Cf + (size_t)blockIdx.z * M * Nn : nullptr;
#pragma unroll
    for (int ni = 0; ni < NI; ni++) {
        const int n = n0 + wn * (NI * 8) + ni * 8 + 2 * (lane & 3);
        const float bv0 = bias ? __ldg(bias + n)     : 0.0f;
        const float bv1 = bias ? __ldg(bias + n + 1) : 0.0f;
        float c0 = 0, c1 = 0, r0 = 0, r1 = 0;
        if (epi) {
            c0 = __ldg(craw + n);  c1 = __ldg(craw + n + 1);
            r0 = __ldg(rho + n);   r1 = __ldg(rho + n + 1);
        }
#pragma unroll
        for (int mi = 0; mi < 4; mi++) {
#pragma unroll
            for (int h = 0; h < 2; h++) {
                const int m = m0 + wm * 64 + mi * 16 + (lane >> 2) + h * 8;
                float v0 = fmaf(sc, acc[mi][ni][2 * h],     bv0);
                float v1 = fmaf(sc, acc[mi][ni][2 * h + 1], bv1);
                if (epi) { v0 = c19f(v0, c0, r0); v1 = c19f(v1, c1, r1); }
                const size_t off = (size_t)m * Nn + n;
                if (CfZ) *(float2*)(CfZ + off) = make_float2(v0, v1);
                if (Chi) {
                    fp16 h0, l0, h1, l1;
                    split2h(v0, h0, l0); split2h(v1, h1, l1);
                    *(__half2*)(Chi + off) = __halves2half2(h0, h1);
                    if (Clo) *(__half2*)(Clo + off) = __halves2half2(l0, l1);
                }
            }
        }
    }
}

#define SMEM_CFG(NI, PA, PB, NSTAGE) \
    (1024 + (NSTAGE) * ((PA) * BM * 64 + (PB) * (NI) * 32 * 64))

// ---------------- launch ----------------
extern "C" void kernel_launch(void* const* d_in, const int* in_sizes, int n_in,
                              void* d_out, int out_size) {
    const float* x    = (const float*)d_in[0];
    const float* cb1  = (const float*)d_in[1];
    const float* cb2  = (const float*)d_in[2];
    const float* W1f  = (const float*)d_in[3];
    const float* W2f  = (const float*)d_in[4];
    const float* b1   = (const float*)d_in[5];
    const float* b2   = (const float*)d_in[6];
    const float* db1  = (const float*)d_in[7];
    const float* db2  = (const float*)d_in[8];
    const float* craw = (const float*)d_in[9];
    const float* rraw = (const float*)d_in[10];
    const int*   W1i  = (const int*)d_in[11];
    const int*   W2i  = (const int*)d_in[12];
    const void*  W1m  = d_in[13];
    const void*  W2m  = d_in[14];

    fp16 *xhi, *xlo, *W1hi, *W1Thi, *W2Thi;
    fp16 *z1hi, *zhi, *zlo, *Mhi;
    int8_t *xloq, *W1Tq;
    float *part, *dvec;
    cudaGetSymbolAddress((void**)&xhi,  g_xhi);   cudaGetSymbolAddress((void**)&xlo,  g_xlo);
    cudaGetSymbolAddress((void**)&xloq, g_xloq);
    cudaGetSymbolAddress((void**)&W1hi, g_W1hi);
    cudaGetSymbolAddress((void**)&W1Thi,g_W1Thi);
    cudaGetSymbolAddress((void**)&W1Tq, g_W1Tq);
    cudaGetSymbolAddress((void**)&W2Thi,g_W2Thi);
    cudaGetSymbolAddress((void**)&z1hi, g_z1hi);
    cudaGetSymbolAddress((void**)&zhi,  g_zhi);   cudaGetSymbolAddress((void**)&zlo,  g_zlo);
    cudaGetSymbolAddress((void**)&part, g_part);
    cudaGetSymbolAddress((void**)&Mhi,  g_Mhi);
    cudaGetSymbolAddress((void**)&dvec, g_dvec);

    float* dec = (float*)d_out;
    float* z   = (float*)d_out + (size_t)NBATCH * IN_DIM;

    cudaFuncSetAttribute((const void*)g1_kernel,
                         cudaFuncAttributeMaxDynamicSharedMemorySize, SMEM_G1);
    cudaFuncSetAttribute((const void*)gemm_fp16_kernel<4,1,1,5>,
                         cudaFuncAttributeMaxDynamicSharedMemorySize, SMEM_CFG(4,1,1,5));
    cudaFuncSetAttribute((const void*)gemm_fp16_kernel<4,2,1,4>,
                         cudaFuncAttributeMaxDynamicSharedMemorySize, SMEM_CFG(4,2,1,4));

    // 1. mask dtype probe + scale zero-init
    detect_mask_kernel<<<1, 256>>>((const unsigned int*)W1m, 4096);

    // 2. fused prepass: split x | dequant W1 | dequant W2 (+ amax atomics)
    prepass_kernel<<<NB_SPLIT + NB_DQ1 + NB_DQ2, 256>>>(
        (const float4*)x, xhi, xlo,
        W1i, W1m, W1f, cb1, W1hi, W1Thi,
        W2i, W2m, W2f, cb2, W2Thi);

    // 3. quantize xlo and Ŵ1T to int8
    quant_kernel<<<NB_QX + NB_QW, 256>>>(xlo, xloq, W1Thi, W1Tq);

    // 4. GM: M̂ = Ŵ1hi @ Ŵ2hi (1-product, K-split 4)   [2048 x 512], K=8192
    gemm_fp16_kernel<4,1,1,5><<<dim3(OUT_DIM / 128, IN_DIM / BM, 4), 256, SMEM_CFG(4,1,1,5)>>>(
        W1hi, nullptr, W2Thi, nullptr, IN_DIM, OUT_DIM, HDIM / 4, HDIM,
        nullptr, nullptr, nullptr, 0, nullptr, nullptr, part, nullptr, nullptr);

    // 5. fused: reduce M partials | dvec = s1*(db1 @ Ŵ1hiᵀ) + db2
    postgm_kernel<<<NB_RM + IN_DIM, 256>>>(part, Mhi, W1hi, db1, db2, cb1, dvec);

    // 6. G1: z1 = c19(s1*(xhi@Ŵ1T + int8(xlo@Ŵ1T)) + b1)   [4096 x 8192], K=2048
    g1_kernel<<<dim3(HDIM / 256, NBATCH / 128), 256, SMEM_G1>>>(
        xhi, xloq, W1Thi, W1Tq, cb1, b1, craw, rraw, z1hi);

    // 7. G2: z = s2*(z1hi @ Ŵ2) + b2      1-product, direct   [4096 x 512], K=8192
    gemm_fp16_kernel<4,1,1,5><<<dim3(OUT_DIM / 128, NBATCH / BM), 256, SMEM_CFG(4,1,1,5)>>>(
        z1hi, nullptr, W2Thi, nullptr, NBATCH, OUT_DIM, HDIM, HDIM,
        cb2, nullptr, b2, 0, nullptr, nullptr, z, zhi, zlo);

    // 8. G5: dec = s1*s2*((zhi+zlo) @ M̂hiᵀ) + dvec  2-product  [4096 x 2048], K=512
    gemm_fp16_kernel<4,2,1,4><<<dim3(IN_DIM / 128, NBATCH / BM), 256, SMEM_CFG(4,2,1,4)>>>(
        zhi, zlo, Mhi, nullptr, NBATCH, IN_DIM, OUT_DIM, OUT_DIM,
        cb1, cb2, dvec, 0, nullptr, nullptr, dec, nullptr, nullptr);
}

// round 16
// speedup vs baseline: 1.0391x; 1.0391x over previous
#include <cuda_runtime.h>
#include <cuda_fp16.h>
#include <cstdint>

#define IN_DIM  2048
#define HDIM    8192
#define OUT_DIM 512
#define NBATCH  4096

typedef __half fp16;

// ---------------- scratch (static __device__ per harness rules) ----------------
__device__ __align__(256) fp16 g_xhi [(size_t)NBATCH * IN_DIM];
__device__ __align__(256) fp16 g_xlo [(size_t)NBATCH * IN_DIM];
__device__ __align__(256) fp16 g_W1hi[(size_t)IN_DIM * HDIM];     // Ŵ1 = W1/s1
__device__ __align__(256) fp16 g_W1Thi[(size_t)HDIM * IN_DIM];
__device__ __align__(256) fp16 g_W2Thi[(size_t)OUT_DIM * HDIM];   // Ŵ2ᵀ = (W2/s2)ᵀ
__device__ __align__(256) fp16 g_z1hi[(size_t)NBATCH * HDIM];
__device__ __align__(256) fp16 g_zhi [(size_t)NBATCH * OUT_DIM];
__device__ __align__(256) fp16 g_zlo [(size_t)NBATCH * OUT_DIM];
// shared partial buffer: GM (8 x 2048 x 512) and G2 (4 x 4096 x 512) = 8M floats each
__device__ __align__(256) float g_part[(size_t)8 * IN_DIM * OUT_DIM];
__device__ __align__(256) fp16 g_Mhi [(size_t)IN_DIM * OUT_DIM];  // M̂ = Ŵ1@Ŵ2
__device__ __align__(256) float g_dvec[IN_DIM];                   // db1@W1ᵀ + db2
__device__ int g_maskmode;

// ---------------- PTX helpers (compute_100-safe) ----------------
__device__ __forceinline__ uint32_t smem_u32(const void* p) {
    uint32_t a;
    asm("{ .reg .u64 t; cvta.to.shared.u64 t, %1; cvt.u32.u64 %0, t; }" : "=r"(a) : "l"(p));
    return a;
}
#define SWZ128(off) ((off) ^ (((off) >> 3) & 0x70))

__device__ __forceinline__ void cp16cp(uint32_t dst, const void* src) {
    asm volatile("cp.async.cg.shared.global [%0], [%1], 16;" :: "r"(dst), "l"(src));
}
#define CP_COMMIT() asm volatile("cp.async.commit_group;" ::: "memory")
#define CP_WAIT(n)  asm volatile("cp.async.wait_group %0;" :: "n"(n) : "memory")

__device__ __forceinline__ void ldsm4(uint32_t a, uint32_t& r0, uint32_t& r1,
                                      uint32_t& r2, uint32_t& r3) {
    asm volatile("ldmatrix.sync.aligned.m8n8.x4.shared.b16 {%0,%1,%2,%3}, [%4];"
                 : "=r"(r0), "=r"(r1), "=r"(r2), "=r"(r3) : "r"(a));
}

__device__ __forceinline__ void mma16816(float* d, const uint32_t* a, const uint32_t* b) {
    asm volatile("mma.sync.aligned.m16n8k16.row.col.f32.f16.f16.f32 "
        "{%0,%1,%2,%3}, {%4,%5,%6,%7}, {%8,%9}, {%0,%1,%2,%3};"
        : "+f"(d[0]), "+f"(d[1]), "+f"(d[2]), "+f"(d[3])
        : "r"(a[0]), "r"(a[1]), "r"(a[2]), "r"(a[3]), "r"(b[0]), "r"(b[1]));
}

// ---------------- mask dtype detection ----------------
__global__ void detect_mask_kernel(const unsigned int* __restrict__ m, int nwords) {
    __shared__ int ok[4];
    if (threadIdx.x < 4) ok[threadIdx.x] = 1;
    __syncthreads();
    for (int i = threadIdx.x; i < nwords; i += blockDim.x) {
        unsigned w = m[i];
        if (!(w == 0u || w == 1u))          atomicAnd(&ok[0], 0);
        if (!(w == 0u || w == 0x3F800000u)) atomicAnd(&ok[1], 0);
        unsigned lo = w & 0xFFFFu, hi = w >> 16;
        if (!((lo == 0u || lo == 0x3F80u) && (hi == 0u || hi == 0x3F80u))) atomicAnd(&ok[2], 0);
        if (!((lo == 0u || lo == 0x3C00u) && (hi == 0u || hi == 0x3C00u))) atomicAnd(&ok[3], 0);
    }
    __syncthreads();
    if (threadIdx.x == 0) {
        int mode = 0;
        if      (ok[0]) mode = 1;
        else if (ok[1]) mode = 2;
        else if (ok[2]) mode = 3;
        else if (ok[3]) mode = 4;
        g_maskmode = mode;
    }
}

__device__ __forceinline__ int read_mask(const void* p, long i, int mode) {
    switch (mode) {
        case 1:  return ((const int*)p)[i] != 0;
        case 2:  return ((const float*)p)[i] != 0.0f;
        case 3:  return ((const unsigned short*)p)[i] != 0;
        case 4:  return ((const unsigned short*)p)[i] != 0;
        default: return ((const unsigned char*)p)[i] != 0;
    }
}

__device__ __forceinline__ void split2h(float v, fp16& h, fp16& l) {
    h = __float2half(v);
    l = __float2half(v - __half2float(h));
}

// ---------------- fused prepass: split x | dequant W1 | dequant W2 ----------
#define NB_SPLIT (NBATCH * IN_DIM / 4 / 256)      // 8192
#define NB_DQ1   ((HDIM / 32) * (IN_DIM / 32))    // 16384
#define NB_DQ2   ((OUT_DIM / 32) * (HDIM / 32))   // 4096

__device__ __forceinline__ void dequant_block(
    const int* __restrict__ idx, const void* __restrict__ mask,
    const float* __restrict__ wf, const float* __restrict__ cb,
    fp16* __restrict__ Whi, fp16* __restrict__ WThi,
    int R, int C, int bx, int by, float tile[32][33]) {
    const int mode = g_maskmode;
    float s = __ldg(cb + 3);
    if (s == 0.0f) s = 1.0f;
    const int c0 = bx * 32;
    const int r0 = by * 32;
    const int tx = threadIdx.x & 31;
    const int ty = threadIdx.x >> 5;      // 0..7
    for (int rr = ty; rr < 32; rr += 8) {
        long off = (long)(r0 + rr) * C + c0 + tx;
        int  m = read_mask(mask, off, mode);
        float v = (m ? cb[idx[off]] : wf[off]) / s;   // exact for codebook
        if (Whi) Whi[off] = __float2half(v);
        tile[rr][tx] = v;
    }
    __syncthreads();
    for (int rr = ty; rr < 32; rr += 8) {
        float v = tile[tx][rr];
        long off = (long)(c0 + rr) * R + r0 + tx;
        WThi[off] = __float2half(v);
    }
}

__global__ void prepass_kernel(
    const float4* __restrict__ x4, fp16* __restrict__ xhi, fp16* __restrict__ xlo,
    const int* __restrict__ W1i, const void* __restrict__ W1m,
    const float* __restrict__ W1f, const float* __restrict__ cb1,
    fp16* __restrict__ W1hi, fp16* __restrict__ W1Thi,
    const int* __restrict__ W2i, const void* __restrict__ W2m,
    const float* __restrict__ W2f, const float* __restrict__ cb2,
    fp16* __restrict__ W2Thi) {
    __shared__ float tile[32][33];
    const int b = blockIdx.x;
    if (b < NB_SPLIT) {
        size_t i = (size_t)b * 256 + threadIdx.x;
        float4 v = x4[i];
        fp16 h0, l0, h1, l1, h2, l2, h3, l3;
        split2h(v.x, h0, l0); split2h(v.y, h1, l1);
        split2h(v.z, h2, l2); split2h(v.w, h3, l3);
        ((__half2*)xhi)[2 * i]     = __halves2half2(h0, h1);
        ((__half2*)xhi)[2 * i + 1] = __halves2half2(h2, h3);
        ((__half2*)xlo)[2 * i]     = __halves2half2(l0, l1);
        ((__half2*)xlo)[2 * i + 1] = __halves2half2(l2, l3);
    } else if (b < NB_SPLIT + NB_DQ1) {
        int j = b - NB_SPLIT;
        dequant_block(W1i, W1m, W1f, cb1, W1hi, W1Thi,
                      IN_DIM, HDIM, j & 255, j >> 8, tile);
    } else {
        int j = b - NB_SPLIT - NB_DQ1;
        dequant_block(W2i, W2m, W2f, cb2, nullptr, W2Thi,
                      HDIM, OUT_DIM, j & 15, j >> 4, tile);
    }
}

// ---------------- fused post-GM: reduce M partials (8-way) | dvec ----------
#define NB_RM ((IN_DIM * OUT_DIM) / 256)          // 4096

__global__ void postgm_kernel(const float* __restrict__ part,
                              fp16* __restrict__ Mhi,
                              const fp16* __restrict__ W1hi,
                              const float* __restrict__ db1, const float* __restrict__ db2,
                              const float* __restrict__ cb1, float* __restrict__ dvec) {
    __shared__ float red[256];
    const int b = blockIdx.x;
    if (b < NB_RM) {
        size_t i = (size_t)b * 256 + threadIdx.x;
        const size_t n = (size_t)IN_DIM * OUT_DIM;
        float v = 0.0f;
#pragma unroll
        for (int p = 0; p < 8; p++) v += part[i + (size_t)p * n];
        Mhi[i] = __float2half(v);
    } else {
        const int j = b - NB_RM;
        float s = __ldg(cb1 + 3);
        if (s == 0.0f) s = 1.0f;
        float sum = 0.0f;
        const size_t base = (size_t)j * HDIM;
        for (int h = threadIdx.x; h < HDIM; h += 256)
            sum += __half2float(W1hi[base + h]) * __ldg(db1 + h);
        red[threadIdx.x] = sum;
        __syncthreads();
        for (int st = 128; st > 0; st >>= 1) {
            if (threadIdx.x < st) red[threadIdx.x] += red[threadIdx.x + st];
            __syncthreads();
        }
        if (threadIdx.x == 0) dvec[j] = fmaf(s, red[0], __ldg(db2 + j));
    }
}

// ---------------- reduce G2 partials: z = s2*Σ + b2, + fp16 split ----------
__global__ void reduce_z_kernel(const float* __restrict__ part,
                                const float* __restrict__ cb2,
                                const float* __restrict__ b2,
                                float* __restrict__ z,
                                fp16* __restrict__ zhi, fp16* __restrict__ zlo) {
    size_t i = (size_t)blockIdx.x * blockDim.x + threadIdx.x;
    const size_t n = (size_t)NBATCH * OUT_DIM;
    if (i < n) {
        float s = __ldg(cb2 + 3);
        if (s == 0.0f) s = 1.0f;
        float acc = part[i] + part[i + n] + part[i + 2 * n] + part[i + 3 * n];
        float v = fmaf(s, acc, __ldg(b2 + (i % OUT_DIM)));
        z[i] = v;
        fp16 h, l; split2h(v, h, l);
        zhi[i] = h; zlo[i] = l;
    }
}

// ---------------- c19 activation ----------------
__device__ __forceinline__ float c19f(float x, float craw, float rhoraw) {
    float c   = fmaxf(craw, 0.1f);
    float rho = fmaxf(rhoraw, 0.0f);
    float L   = 6.0f * c;
    float s   = x / c;
    float n   = floorf(s);
    float t   = s - n;
    float h   = t * (1.0f - t);
    float sgn = (fmodf(n, 2.0f) == 0.0f) ? 1.0f : -1.0f;
    float interior = c * (sgn * h + rho * h * h);
    return (x >= L) ? (x - L) : ((x <= -L) ? (x + L) : interior);
}

// ---------------- fp16 multi-product GEMM ----------------
// acc = Ahi*Bhi (+ Alo*Bhi if PA==2) (+ Ahi*Blo if PB==2)
// C = sa*sb*acc + bias (nullable). B K-major. Block 128 x (NI*32), 8 warps 2x4.
// gridDim.z = K-splits (partials at Cf + z*M*Nn). ldk = row stride of A and B.
#define BM 128
#define BKK 32

template<int NI, int PA, int PB, int NSTAGE>
__global__ void __launch_bounds__(256, 1)
gemm_fp16_kernel(const fp16* __restrict__ Ahi, const fp16* __restrict__ Alo,
                 const fp16* __restrict__ Bhi, const fp16* __restrict__ Blo,
                 int M, int Nn, int Klen, int ldk,
                 const float* __restrict__ cba, const float* __restrict__ cbb,
                 const float* __restrict__ bias, int epi,
                 const float* __restrict__ craw, const float* __restrict__ rho,
                 float* __restrict__ Cf, fp16* __restrict__ Chi, fp16* __restrict__ Clo) {
    constexpr int BN = NI * 32;
    constexpr int A_BYTES = BM * 64;
    constexpr int B_BYTES = BN * 64;
    constexpr int STAGE_BYTES = PA * A_BYTES + PB * B_BYTES;
    extern __shared__ char smem[];
    const uint32_t sbase = smem_u32(smem);
    const uint32_t tbase = (sbase + 1023u) & ~1023u;
    const int tid  = threadIdx.x;
    const int wid  = tid >> 5;
    const int lane = tid & 31;
    const int wm = wid & 1;
    const int wn = wid >> 1;

    const int m0 = blockIdx.y * BM;
    const int n0 = blockIdx.x * BN;
    const size_t kbase = (size_t)blockIdx.z * Klen;

    float sa = cba ? __ldg(cba + 3) : 1.0f;  if (sa == 0.0f) sa = 1.0f;
    float sb = cbb ? __ldg(cbb + 3) : 1.0f;  if (sb == 0.0f) sb = 1.0f;
    const float sc = sa * sb;

    uint32_t sAh[NSTAGE], sAl[NSTAGE], sBh[NSTAGE], sBl[NSTAGE];
#pragma unroll
    for (int s = 0; s < NSTAGE; s++) {
        uint32_t b = tbase + s * STAGE_BYTES;
        sAh[s] = b;
        sAl[s] = b + A_BYTES;
        sBh[s] = b + PA * A_BYTES;
        sBl[s] = b + PA * A_BYTES + B_BYTES;
    }

    const int ITERS = Klen / BKK;

    float acc[4][NI][4];
#pragma unroll
    for (int i = 0; i < 4; i++)
#pragma unroll
        for (int j = 0; j < NI; j++)
#pragma unroll
            for (int r = 0; r < 4; r++) acc[i][j][r] = 0.0f;

    auto fill = [&](int kc) {
        const int s = kc % NSTAGE;
        const size_t k0 = kbase + (size_t)kc * BKK;
#pragma unroll
        for (int i = 0; i < 2; i++) {
            int ch = tid + i * 256;
            int r = ch >> 2, c = ch & 3;
            uint32_t so = SWZ128(r * 64 + c * 16);
            const char* pA = (const char*)(Ahi + (size_t)(m0 + r) * ldk + k0) + c * 16;
            cp16cp(sAh[s] + so, pA);
            if (PA == 2) {
                const char* pL = (const char*)(Alo + (size_t)(m0 + r) * ldk + k0) + c * 16;
                cp16cp(sAl[s] + so, pL);
            }
        }
#pragma unroll
        for (int i = 0; i < NI / 2; i++) {
            int ch = tid + i * 256;
            int r = ch >> 2, c = ch & 3;
            uint32_t so = SWZ128(r * 64 + c * 16);
            const char* pB = (const char*)(Bhi + (size_t)(n0 + r) * ldk + k0) + c * 16;
            cp16cp(sBh[s] + so, pB);
            if (PB == 2) {
                const char* pBl = (const char*)(Blo + (size_t)(n0 + r) * ldk + k0) + c * 16;
                cp16cp(sBl[s] + so, pBl);
            }
        }
    };

    for (int it = 0; it < NSTAGE - 1; it++) { fill(it); CP_COMMIT(); }

    for (int it = 0; it < ITERS; it++) {
        CP_WAIT(NSTAGE - 2);
        __syncthreads();
        if (it + NSTAGE - 1 < ITERS) fill(it + NSTAGE - 1);
        CP_COMMIT();

        const int s = it % NSTAGE;
#pragma unroll
        for (int kk = 0; kk < 2; kk++) {
            uint32_t afh[4][4], afl[4][4];
#pragma unroll
            for (int mi = 0; mi < 4; mi++) {
                int row = wm * 64 + mi * 16 + (lane & 15);
                int ch  = kk * 2 + (lane >> 4);
                uint32_t so = SWZ128(row * 64 + ch * 16);
                ldsm4(sAh[s] + so, afh[mi][0], afh[mi][1], afh[mi][2], afh[mi][3]);
                if (PA == 2)
                    ldsm4(sAl[s] + so, afl[mi][0], afl[mi][1], afl[mi][2], afl[mi][3]);
            }
            uint32_t bfh[NI][2], bfl[NI][2];
#pragma unroll
            for (int p = 0; p < NI / 2; p++) {
                int g   = lane >> 3;
                int row = wn * (NI * 8) + (p * 2 + (g >> 1)) * 8 + (lane & 7);
                int ch  = kk * 2 + (g & 1);
                uint32_t so = SWZ128(row * 64 + ch * 16);
                uint32_t r0, r1, r2, r3;
                ldsm4(sBh[s] + so, r0, r1, r2, r3);
                bfh[p * 2][0] = r0;  bfh[p * 2][1] = r1;
                bfh[p * 2 + 1][0] = r2; bfh[p * 2 + 1][1] = r3;
                if (PB == 2) {
                    ldsm4(sBl[s] + so, r0, r1, r2, r3);
                    bfl[p * 2][0] = r0;  bfl[p * 2][1] = r1;
                    bfl[p * 2 + 1][0] = r2; bfl[p * 2 + 1][1] = r3;
                }
            }
#pragma unroll
            for (int mi = 0; mi < 4; mi++)
#pragma unroll
                for (int ni = 0; ni < NI; ni++)
                    mma16816(acc[mi][ni], afh[mi], bfh[ni]);
            if (PA == 2) {
#pragma unroll
                for (int mi = 0; mi < 4; mi++)
#pragma unroll
                    for (int ni = 0; ni < NI; ni++)
                        mma16816(acc[mi][ni], afl[mi], bfh[ni]);
            }
            if (PB == 2) {
#pragma unroll
                for (int mi = 0; mi < 4; mi++)
#pragma unroll
                    for (int ni = 0; ni < NI; ni++)
                        mma16816(acc[mi][ni], afh[mi], bfl[ni]);
            }
        }
    }

    float* CfZ = Cf ? Cf + (size_t)blockIdx.z * M * Nn : nullptr;
#pragma unroll
    for (int ni = 0; ni < NI; ni++) {
        const int n = n0 + wn * (NI * 8) + ni * 8 + 2 * (lane & 3);
        const float bv0 = bias ? __ldg(bias + n)     : 0.0f;
        const float bv1 = bias ? __ldg(bias + n + 1) : 0.0f;
        float c0 = 0, c1 = 0, r0 = 0, r1 = 0;
        if (epi) {
            c0 = __ldg(craw + n);  c1 = __ldg(craw + n + 1);
            r0 = __ldg(rho + n);   r1 = __ldg(rho + n + 1);
        }
#pragma unroll
        for (int mi = 0; mi < 4; mi++) {
#pragma unroll
            for (int h = 0; h < 2; h++) {
                const int m = m0 + wm * 64 + mi * 16 + (lane >> 2) + h * 8;
                float v0 = fmaf(sc, acc[mi][ni][2 * h],     bv0);
                float v1 = fmaf(sc, acc[mi][ni][2 * h + 1], bv1);
                if (epi) { v0 = c19f(v0, c0, r0); v1 = c19f(v1, c1, r1); }
                const size_t off = (size_t)m * Nn + n;
                if (CfZ) *(float2*)(CfZ + off) = make_float2(v0, v1);
                if (Chi) {
                    fp16 h0, l0, h1, l1;
                    split2h(v0, h0, l0); split2h(v1, h1, l1);
                    *(__half2*)(Chi + off) = __halves2half2(h0, h1);
                    if (Clo) *(__half2*)(Clo + off) = __halves2half2(l0, l1);
                }
            }
        }
    }
}

#define SMEM_CFG(NI, PA, PB, NSTAGE) \
    (1024 + (NSTAGE) * ((PA) * BM * 64 + (PB) * (NI) * 32 * 64))

// ---------------- launch ----------------
extern "C" void kernel_launch(void* const* d_in, const int* in_sizes, int n_in,
                              void* d_out, int out_size) {
    const float* x    = (const float*)d_in[0];
    const float* cb1  = (const float*)d_in[1];
    const float* cb2  = (const float*)d_in[2];
    const float* W1f  = (const float*)d_in[3];
    const float* W2f  = (const float*)d_in[4];
    const float* b1   = (const float*)d_in[5];
    const float* b2   = (const float*)d_in[6];
    const float* db1  = (const float*)d_in[7];
    const float* db2  = (const float*)d_in[8];
    const float* craw = (const float*)d_in[9];
    const float* rraw = (const float*)d_in[10];
    const int*   W1i  = (const int*)d_in[11];
    const int*   W2i  = (const int*)d_in[12];
    const void*  W1m  = d_in[13];
    const void*  W2m  = d_in[14];

    fp16 *xhi, *xlo, *W1hi, *W1Thi, *W2Thi;
    fp16 *z1hi, *zhi, *zlo, *Mhi;
    float *part, *dvec;
    cudaGetSymbolAddress((void**)&xhi,  g_xhi);   cudaGetSymbolAddress((void**)&xlo,  g_xlo);
    cudaGetSymbolAddress((void**)&W1hi, g_W1hi);
    cudaGetSymbolAddress((void**)&W1Thi,g_W1Thi);
    cudaGetSymbolAddress((void**)&W2Thi,g_W2Thi);
    cudaGetSymbolAddress((void**)&z1hi, g_z1hi);
    cudaGetSymbolAddress((void**)&zhi,  g_zhi);   cudaGetSymbolAddress((void**)&zlo,  g_zlo);
    cudaGetSymbolAddress((void**)&part, g_part);
    cudaGetSymbolAddress((void**)&Mhi,  g_Mhi);
    cudaGetSymbolAddress((void**)&dvec, g_dvec);

    float* dec = (float*)d_out;
    float* z   = (float*)d_out + (size_t)NBATCH * IN_DIM;

    cudaFuncSetAttribute((const void*)gemm_fp16_kernel<8,2,1,4>,
                         cudaFuncAttributeMaxDynamicSharedMemorySize, SMEM_CFG(8,2,1,4));
    cudaFuncSetAttribute((const void*)gemm_fp16_kernel<8,1,1,4>,
                         cudaFuncAttributeMaxDynamicSharedMemorySize, SMEM_CFG(8,1,1,4));

    // 1. mask dtype probe
    detect_mask_kernel<<<1, 256>>>((const unsigned int*)W1m, 4096);

    // 2. fused prepass: split x | dequant W1 | dequant W2 (overlapped)
    prepass_kernel<<<NB_SPLIT + NB_DQ1 + NB_DQ2, 256>>>(
        (const float4*)x, xhi, xlo,
        W1i, W1m, W1f, cb1, W1hi, W1Thi,
        W2i, W2m, W2f, cb2, W2Thi);

    // 3. GM: M̂ = Ŵ1hi @ Ŵ2hi partials (NI=8, K-split 8)   [2048 x 512], K=8192
    gemm_fp16_kernel<8,1,1,4><<<dim3(OUT_DIM / 256, IN_DIM / BM, 8), 256, SMEM_CFG(8,1,1,4)>>>(
        W1hi, nullptr, W2Thi, nullptr, IN_DIM, OUT_DIM, HDIM / 8, HDIM,
        nullptr, nullptr, nullptr, 0, nullptr, nullptr, part, nullptr, nullptr);

    // 4. fused: reduce M partials (8-way) | dvec = s1*(db1 @ Ŵ1hiᵀ) + db2
    postgm_kernel<<<NB_RM + IN_DIM, 256>>>(part, Mhi, W1hi, db1, db2, cb1, dvec);

    // 5. G1: z1 = c19(s1*(x @ Ŵ1) + b1)   2-product   [4096 x 8192], K=2048
    gemm_fp16_kernel<8,2,1,4><<<dim3(HDIM / 256, NBATCH / BM), 256, SMEM_CFG(8,2,1,4)>>>(
        xhi, xlo, W1Thi, nullptr, NBATCH, HDIM, IN_DIM, IN_DIM,
        cb1, nullptr, b1, 1, craw, rraw, nullptr, z1hi, nullptr);

    // 6. G2: partials of z1hi @ Ŵ2 (NI=8, K-split 4)   [4096 x 512], K=8192
    gemm_fp16_kernel<8,1,1,4><<<dim3(OUT_DIM / 256, NBATCH / BM, 4), 256, SMEM_CFG(8,1,1,4)>>>(
        z1hi, nullptr, W2Thi, nullptr, NBATCH, OUT_DIM, HDIM / 4, HDIM,
        nullptr, nullptr, nullptr, 0, nullptr, nullptr, part, nullptr, nullptr);

    // 7. reduce: z = s2*Σpartials + b2, + fp16 split
    {
        size_t n = (size_t)NBATCH * OUT_DIM;
        reduce_z_kernel<<<(unsigned)((n + 255) / 256), 256>>>(part, cb2, b2, z, zhi, zlo);
    }

    // 8. G5: dec = s1*s2*((zhi+zlo) @ M̂hiᵀ) + dvec  (NI=8, 2-product) [4096 x 2048], K=512
    gemm_fp16_kernel<8,2,1,4><<<dim3(IN_DIM / 256, NBATCH / BM), 256, SMEM_CFG(8,2,1,4)>>>(
        zhi, zlo, Mhi, nullptr, NBATCH, IN_DIM, OUT_DIM, OUT_DIM,
        cb1, cb2, dvec, 0, nullptr, nullptr, dec, nullptr, nullptr);
}

// round 17
// speedup vs baseline: 1.0828x; 1.0421x over previous
#include <cuda_runtime.h>
#include <cuda_fp16.h>
#include <cstdint>

#define IN_DIM  2048
#define HDIM    8192
#define OUT_DIM 512
#define NBATCH  4096

typedef __half fp16;

// ---------------- scratch (static __device__ per harness rules) ----------------
__device__ __align__(256) fp16 g_xhi [(size_t)NBATCH * IN_DIM];
__device__ __align__(256) fp16 g_xlo [(size_t)NBATCH * IN_DIM];
__device__ __align__(256) fp16 g_W1hi[(size_t)IN_DIM * HDIM];     // Ŵ1 = W1/s1
__device__ __align__(256) fp16 g_W1Thi[(size_t)HDIM * IN_DIM];
__device__ __align__(256) fp16 g_W2Thi[(size_t)OUT_DIM * HDIM];   // Ŵ2ᵀ = (W2/s2)ᵀ
__device__ __align__(256) fp16 g_z1hi[(size_t)NBATCH * HDIM];
__device__ __align__(256) fp16 g_zhi [(size_t)NBATCH * OUT_DIM];
// partial buffer: GM 4 x (2048x512) at [0, 4M); G2 4 x (4096x512) at [4M, 12M)
__device__ __align__(256) float g_part[(size_t)12 * 1024 * 1024];
__device__ __align__(256) fp16 g_Mhi [(size_t)IN_DIM * OUT_DIM];  // M̂ = Ŵ1@Ŵ2
__device__ __align__(256) float g_dvec[IN_DIM];                   // db1@W1ᵀ + db2
__device__ int g_maskmode;

#define GM_PART_N  ((size_t)IN_DIM * OUT_DIM)     // 1M
#define G2_PART_N  ((size_t)NBATCH * OUT_DIM)     // 2M
#define G2_PART_OFF ((size_t)4 * GM_PART_N)       // 4M floats

// ---------------- PTX helpers (compute_100-safe) ----------------
__device__ __forceinline__ uint32_t smem_u32(const void* p) {
    uint32_t a;
    asm("{ .reg .u64 t; cvta.to.shared.u64 t, %1; cvt.u32.u64 %0, t; }" : "=r"(a) : "l"(p));
    return a;
}
#define SWZ128(off) ((off) ^ (((off) >> 3) & 0x70))

__device__ __forceinline__ void cp16cp(uint32_t dst, const void* src) {
    asm volatile("cp.async.cg.shared.global [%0], [%1], 16;" :: "r"(dst), "l"(src));
}
#define CP_COMMIT() asm volatile("cp.async.commit_group;" ::: "memory")
#define CP_WAIT(n)  asm volatile("cp.async.wait_group %0;" :: "n"(n) : "memory")

__device__ __forceinline__ void ldsm4(uint32_t a, uint32_t& r0, uint32_t& r1,
                                      uint32_t& r2, uint32_t& r3) {
    asm volatile("ldmatrix.sync.aligned.m8n8.x4.shared.b16 {%0,%1,%2,%3}, [%4];"
                 : "=r"(r0), "=r"(r1), "=r"(r2), "=r"(r3) : "r"(a));
}

__device__ __forceinline__ void mma16816(float* d, const uint32_t* a, const uint32_t* b) {
    asm volatile("mma.sync.aligned.m16n8k16.row.col.f32.f16.f16.f32 "
        "{%0,%1,%2,%3}, {%4,%5,%6,%7}, {%8,%9}, {%0,%1,%2,%3};"
        : "+f"(d[0]), "+f"(d[1]), "+f"(d[2]), "+f"(d[3])
        : "r"(a[0]), "r"(a[1]), "r"(a[2]), "r"(a[3]), "r"(b[0]), "r"(b[1]));
}

// ---------------- mask dtype detection ----------------
__global__ void detect_mask_kernel(const unsigned int* __restrict__ m, int nwords) {
    __shared__ int ok[4];
    if (threadIdx.x < 4) ok[threadIdx.x] = 1;
    __syncthreads();
    for (int i = threadIdx.x; i < nwords; i += blockDim.x) {
        unsigned w = m[i];
        if (!(w == 0u || w == 1u))          atomicAnd(&ok[0], 0);
        if (!(w == 0u || w == 0x3F800000u)) atomicAnd(&ok[1], 0);
        unsigned lo = w & 0xFFFFu, hi = w >> 16;
        if (!((lo == 0u || lo == 0x3F80u) && (hi == 0u || hi == 0x3F80u))) atomicAnd(&ok[2], 0);
        if (!((lo == 0u || lo == 0x3C00u) && (hi == 0u || hi == 0x3C00u))) atomicAnd(&ok[3], 0);
    }
    __syncthreads();
    if (threadIdx.x == 0) {
        int mode = 0;
        if      (ok[0]) mode = 1;
        else if (ok[1]) mode = 2;
        else if (ok[2]) mode = 3;
        else if (ok[3]) mode = 4;
        g_maskmode = mode;
    }
}

__device__ __forceinline__ int read_mask(const void* p, long i, int mode) {
    switch (mode) {
        case 1:  return ((const int*)p)[i] != 0;
        case 2:  return ((const float*)p)[i] != 0.0f;
        case 3:  return ((const unsigned short*)p)[i] != 0;
        case 4:  return ((const unsigned short*)p)[i] != 0;
        default: return ((const unsigned char*)p)[i] != 0;
    }
}

__device__ __forceinline__ void split2h(float v, fp16& h, fp16& l) {
    h = __float2half(v);
    l = __float2half(v - __half2float(h));
}

// ---------------- fused prepass: split x | dequant W1 | dequant W2 ----------
#define NB_SPLIT (NBATCH * IN_DIM / 4 / 256)      // 8192
#define NB_DQ1   ((HDIM / 32) * (IN_DIM / 32))    // 16384
#define NB_DQ2   ((OUT_DIM / 32) * (HDIM / 32))   // 4096

__device__ __forceinline__ void dequant_block(
    const int* __restrict__ idx, const void* __restrict__ mask,
    const float* __restrict__ wf, const float* __restrict__ cb,
    fp16* __restrict__ Whi, fp16* __restrict__ WThi,
    int R, int C, int bx, int by, float tile[32][33]) {
    const int mode = g_maskmode;
    float s = __ldg(cb + 3);
    if (s == 0.0f) s = 1.0f;
    const int c0 = bx * 32;
    const int r0 = by * 32;
    const int tx = threadIdx.x & 31;
    const int ty = threadIdx.x >> 5;      // 0..7
    for (int rr = ty; rr < 32; rr += 8) {
        long off = (long)(r0 + rr) * C + c0 + tx;
        int  m = read_mask(mask, off, mode);
        float v = (m ? cb[idx[off]] : wf[off]) / s;   // exact for codebook
        if (Whi) Whi[off] = __float2half(v);
        tile[rr][tx] = v;
    }
    __syncthreads();
    for (int rr = ty; rr < 32; rr += 8) {
        float v = tile[tx][rr];
        long off = (long)(c0 + rr) * R + r0 + tx;
        WThi[off] = __float2half(v);
    }
}

__global__ void prepass_kernel(
    const float4* __restrict__ x4, fp16* __restrict__ xhi, fp16* __restrict__ xlo,
    const int* __restrict__ W1i, const void* __restrict__ W1m,
    const float* __restrict__ W1f, const float* __restrict__ cb1,
    fp16* __restrict__ W1hi, fp16* __restrict__ W1Thi,
    const int* __restrict__ W2i, const void* __restrict__ W2m,
    const float* __restrict__ W2f, const float* __restrict__ cb2,
    fp16* __restrict__ W2Thi) {
    __shared__ float tile[32][33];
    const int b = blockIdx.x;
    if (b < NB_SPLIT) {
        size_t i = (size_t)b * 256 + threadIdx.x;
        float4 v = x4[i];
        fp16 h0, l0, h1, l1, h2, l2, h3, l3;
        split2h(v.x, h0, l0); split2h(v.y, h1, l1);
        split2h(v.z, h2, l2); split2h(v.w, h3, l3);
        ((__half2*)xhi)[2 * i]     = __halves2half2(h0, h1);
        ((__half2*)xhi)[2 * i + 1] = __halves2half2(h2, h3);
        ((__half2*)xlo)[2 * i]     = __halves2half2(l0, l1);
        ((__half2*)xlo)[2 * i + 1] = __halves2half2(l2, l3);
    } else if (b < NB_SPLIT + NB_DQ1) {
        int j = b - NB_SPLIT;
        dequant_block(W1i, W1m, W1f, cb1, W1hi, W1Thi,
                      IN_DIM, HDIM, j & 255, j >> 8, tile);
    } else {
        int j = b - NB_SPLIT - NB_DQ1;
        dequant_block(W2i, W2m, W2f, cb2, nullptr, W2Thi,
                      HDIM, OUT_DIM, j & 15, j >> 4, tile);
    }
}

// ---------------- fused post: reduce M (4-way) | dvec | reduce z (4-way) ----
#define NB_RM ((IN_DIM * OUT_DIM) / 256)          // 4096
#define NB_RZ ((NBATCH * OUT_DIM) / 256)          // 8192

__global__ void postcombo_kernel(const float* __restrict__ part,
                                 fp16* __restrict__ Mhi,
                                 const fp16* __restrict__ W1hi,
                                 const float* __restrict__ db1, const float* __restrict__ db2,
                                 const float* __restrict__ cb1, float* __restrict__ dvec,
                                 const float* __restrict__ cb2, const float* __restrict__ b2,
                                 float* __restrict__ z, fp16* __restrict__ zhi) {
    __shared__ float red[256];
    const int b = blockIdx.x;
    if (b < NB_RM) {
        size_t i = (size_t)b * 256 + threadIdx.x;
        float v = 0.0f;
#pragma unroll
        for (int p = 0; p < 4; p++) v += part[i + (size_t)p * GM_PART_N];
        Mhi[i] = __float2half(v);
    } else if (b < NB_RM + IN_DIM) {
        const int j = b - NB_RM;
        float s = __ldg(cb1 + 3);
        if (s == 0.0f) s = 1.0f;
        float sum = 0.0f;
        const size_t base = (size_t)j * HDIM;
        for (int h = threadIdx.x; h < HDIM; h += 256)
            sum += __half2float(W1hi[base + h]) * __ldg(db1 + h);
        red[threadIdx.x] = sum;
        __syncthreads();
        for (int st = 128; st > 0; st >>= 1) {
            if (threadIdx.x < st) red[threadIdx.x] += red[threadIdx.x + st];
            __syncthreads();
        }
        if (threadIdx.x == 0) dvec[j] = fmaf(s, red[0], __ldg(db2 + j));
    } else {
        size_t i = (size_t)(b - NB_RM - IN_DIM) * 256 + threadIdx.x;
        const float* pg2 = part + G2_PART_OFF;
        float s = __ldg(cb2 + 3);
        if (s == 0.0f) s = 1.0f;
        float acc = 0.0f;
#pragma unroll
        for (int p = 0; p < 4; p++) acc += pg2[i + (size_t)p * G2_PART_N];
        float v = fmaf(s, acc, __ldg(b2 + (i % OUT_DIM)));
        z[i] = v;
        zhi[i] = __float2half(v);
    }
}

// ---------------- c19 activation ----------------
__device__ __forceinline__ float c19f(float x, float craw, float rhoraw) {
    float c   = fmaxf(craw, 0.1f);
    float rho = fmaxf(rhoraw, 0.0f);
    float L   = 6.0f * c;
    float s   = x / c;
    float n   = floorf(s);
    float t   = s - n;
    float h   = t * (1.0f - t);
    float sgn = (fmodf(n, 2.0f) == 0.0f) ? 1.0f : -1.0f;
    float interior = c * (sgn * h + rho * h * h);
    return (x >= L) ? (x - L) : ((x <= -L) ? (x + L) : interior);
}

// ---------------- fp16 multi-product GEMM ----------------
// acc = Ahi*Bhi (+ Alo*Bhi if PA==2) (+ Ahi*Blo if PB==2)
// C = sa*sb*acc + bias (nullable). B K-major. Block 128 x (NI*32), 8 warps 2x4.
// gridDim.z = K-splits (partials at Cf + z*M*Nn). ldk = row stride of A and B.
#define BM 128
#define BKK 32

template<int NI, int PA, int PB, int NSTAGE>
__global__ void __launch_bounds__(256, 1)
gemm_fp16_kernel(const fp16* __restrict__ Ahi, const fp16* __restrict__ Alo,
                 const fp16* __restrict__ Bhi, const fp16* __restrict__ Blo,
                 int M, int Nn, int Klen, int ldk,
                 const float* __restrict__ cba, const float* __restrict__ cbb,
                 const float* __restrict__ bias, int epi,
                 const float* __restrict__ craw, const float* __restrict__ rho,
                 float* __restrict__ Cf, fp16* __restrict__ Chi, fp16* __restrict__ Clo) {
    constexpr int BN = NI * 32;
    constexpr int A_BYTES = BM * 64;
    constexpr int B_BYTES = BN * 64;
    constexpr int STAGE_BYTES = PA * A_BYTES + PB * B_BYTES;
    extern __shared__ char smem[];
    const uint32_t sbase = smem_u32(smem);
    const uint32_t tbase = (sbase + 1023u) & ~1023u;
    const int tid  = threadIdx.x;
    const int wid  = tid >> 5;
    const int lane = tid & 31;
    const int wm = wid & 1;
    const int wn = wid >> 1;

    const int m0 = blockIdx.y * BM;
    const int n0 = blockIdx.x * BN;
    const size_t kbase = (size_t)blockIdx.z * Klen;

    float sa = cba ? __ldg(cba + 3) : 1.0f;  if (sa == 0.0f) sa = 1.0f;
    float sb = cbb ? __ldg(cbb + 3) : 1.0f;  if (sb == 0.0f) sb = 1.0f;
    const float sc = sa * sb;

    uint32_t sAh[NSTAGE], sAl[NSTAGE], sBh[NSTAGE], sBl[NSTAGE];
#pragma unroll
    for (int s = 0; s < NSTAGE; s++) {
        uint32_t b = tbase + s * STAGE_BYTES;
        sAh[s] = b;
        sAl[s] = b + A_BYTES;
        sBh[s] = b + PA * A_BYTES;
        sBl[s] = b + PA * A_BYTES + B_BYTES;
    }

    const int ITERS = Klen / BKK;

    float acc[4][NI][4];
#pragma unroll
    for (int i = 0; i < 4; i++)
#pragma unroll
        for (int j = 0; j < NI; j++)
#pragma unroll
            for (int r = 0; r < 4; r++) acc[i][j][r] = 0.0f;

    auto fill = [&](int kc) {
        const int s = kc % NSTAGE;
        const size_t k0 = kbase + (size_t)kc * BKK;
#pragma unroll
        for (int i = 0; i < 2; i++) {
            int ch = tid + i * 256;
            int r = ch >> 2, c = ch & 3;
            uint32_t so = SWZ128(r * 64 + c * 16);
            const char* pA = (const char*)(Ahi + (size_t)(m0 + r) * ldk + k0) + c * 16;
            cp16cp(sAh[s] + so, pA);
            if (PA == 2) {
                const char* pL = (const char*)(Alo + (size_t)(m0 + r) * ldk + k0) + c * 16;
                cp16cp(sAl[s] + so, pL);
            }
        }
#pragma unroll
        for (int i = 0; i < NI / 2; i++) {
            int ch = tid + i * 256;
            int r = ch >> 2, c = ch & 3;
            uint32_t so = SWZ128(r * 64 + c * 16);
            const char* pB = (const char*)(Bhi + (size_t)(n0 + r) * ldk + k0) + c * 16;
            cp16cp(sBh[s] + so, pB);
            if (PB == 2) {
                const char* pBl = (const char*)(Blo + (size_t)(n0 + r) * ldk + k0) + c * 16;
                cp16cp(sBl[s] + so, pBl);
            }
        }
    };

    for (int it = 0; it < NSTAGE - 1; it++) { fill(it); CP_COMMIT(); }

    for (int it = 0; it < ITERS; it++) {
        CP_WAIT(NSTAGE - 2);
        __syncthreads();
        if (it + NSTAGE - 1 < ITERS) fill(it + NSTAGE - 1);
        CP_COMMIT();

        const int s = it % NSTAGE;
#pragma unroll
        for (int kk = 0; kk < 2; kk++) {
            uint32_t afh[4][4], afl[4][4];
#pragma unroll
            for (int mi = 0; mi < 4; mi++) {
                int row = wm * 64 + mi * 16 + (lane & 15);
                int ch  = kk * 2 + (lane >> 4);
                uint32_t so = SWZ128(row * 64 + ch * 16);
                ldsm4(sAh[s] + so, afh[mi][0], afh[mi][1], afh[mi][2], afh[mi][3]);
                if (PA == 2)
                    ldsm4(sAl[s] + so, afl[mi][0], afl[mi][1], afl[mi][2], afl[mi][3]);
            }
            uint32_t bfh[NI][2], bfl[NI][2];
#pragma unroll
            for (int p = 0; p < NI / 2; p++) {
                int g   = lane >> 3;
                int row = wn * (NI * 8) + (p * 2 + (g >> 1)) * 8 + (lane & 7);
                int ch  = kk * 2 + (g & 1);
                uint32_t so = SWZ128(row * 64 + ch * 16);
                uint32_t r0, r1, r2, r3;
                ldsm4(sBh[s] + so, r0, r1, r2, r3);
                bfh[p * 2][0] = r0;  bfh[p * 2][1] = r1;
                bfh[p * 2 + 1][0] = r2; bfh[p * 2 + 1][1] = r3;
                if (PB == 2) {
                    ldsm4(sBl[s] + so, r0, r1, r2, r3);
                    bfl[p * 2][0] = r0;  bfl[p * 2][1] = r1;
                    bfl[p * 2 + 1][0] = r2; bfl[p * 2 + 1][1] = r3;
                }
            }
#pragma unroll
            for (int mi = 0; mi < 4; mi++)
#pragma unroll
                for (int ni = 0; ni < NI; ni++)
                    mma16816(acc[mi][ni], afh[mi], bfh[ni]);
            if (PA == 2) {
#pragma unroll
                for (int mi = 0; mi < 4; mi++)
#pragma unroll
                    for (int ni = 0; ni < NI; ni++)
                        mma16816(acc[mi][ni], afl[mi], bfh[ni]);
            }
            if (PB == 2) {
#pragma unroll
                for (int mi = 0; mi < 4; mi++)
#pragma unroll
                    for (int ni = 0; ni < NI; ni++)
                        mma16816(acc[mi][ni], afh[mi], bfl[ni]);
            }
        }
    }

    float* CfZ = Cf ? Cf + (size_t)blockIdx.z * M * Nn : nullptr;
#pragma unroll
    for (int ni = 0; ni < NI; ni++) {
        const int n = n0 + wn * (NI * 8) + ni * 8 + 2 * (lane & 3);
        const float bv0 = bias ? __ldg(bias + n)     : 0.0f;
        const float bv1 = bias ? __ldg(bias + n + 1) : 0.0f;
        float c0 = 0, c1 = 0, r0 = 0, r1 = 0;
        if (epi) {
            c0 = __ldg(craw + n);  c1 = __ldg(craw + n + 1);
            r0 = __ldg(rho + n);   r1 = __ldg(rho + n + 1);
        }
#pragma unroll
        for (int mi = 0; mi < 4; mi++) {
#pragma unroll
            for (int h = 0; h < 2; h++) {
                const int m = m0 + wm * 64 + mi * 16 + (lane >> 2) + h * 8;
                float v0 = fmaf(sc, acc[mi][ni][2 * h],     bv0);
                float v1 = fmaf(sc, acc[mi][ni][2 * h + 1], bv1);
                if (epi) { v0 = c19f(v0, c0, r0); v1 = c19f(v1, c1, r1); }
                const size_t off = (size_t)m * Nn + n;
                if (CfZ) *(float2*)(CfZ + off) = make_float2(v0, v1);
                if (Chi) {
                    fp16 h0, l0, h1, l1;
                    split2h(v0, h0, l0); split2h(v1, h1, l1);
                    *(__half2*)(Chi + off) = __halves2half2(h0, h1);
                    if (Clo) *(__half2*)(Clo + off) = __halves2half2(l0, l1);
                }
            }
        }
    }
}

#define SMEM_CFG(NI, PA, PB, NSTAGE) \
    (1024 + (NSTAGE) * ((PA) * BM * 64 + (PB) * (NI) * 32 * 64))

// ---------------- launch ----------------
extern "C" void kernel_launch(void* const* d_in, const int* in_sizes, int n_in,
                              void* d_out, int out_size) {
    const float* x    = (const float*)d_in[0];
    const float* cb1  = (const float*)d_in[1];
    const float* cb2  = (const float*)d_in[2];
    const float* W1f  = (const float*)d_in[3];
    const float* W2f  = (const float*)d_in[4];
    const float* b1   = (const float*)d_in[5];
    const float* b2   = (const float*)d_in[6];
    const float* db1  = (const float*)d_in[7];
    const float* db2  = (const float*)d_in[8];
    const float* craw = (const float*)d_in[9];
    const float* rraw = (const float*)d_in[10];
    const int*   W1i  = (const int*)d_in[11];
    const int*   W2i  = (const int*)d_in[12];
    const void*  W1m  = d_in[13];
    const void*  W2m  = d_in[14];

    fp16 *xhi, *xlo, *W1hi, *W1Thi, *W2Thi;
    fp16 *z1hi, *zhi, *Mhi;
    float *part, *dvec;
    cudaGetSymbolAddress((void**)&xhi,  g_xhi);   cudaGetSymbolAddress((void**)&xlo,  g_xlo);
    cudaGetSymbolAddress((void**)&W1hi, g_W1hi);
    cudaGetSymbolAddress((void**)&W1Thi,g_W1Thi);
    cudaGetSymbolAddress((void**)&W2Thi,g_W2Thi);
    cudaGetSymbolAddress((void**)&z1hi, g_z1hi);
    cudaGetSymbolAddress((void**)&zhi,  g_zhi);
    cudaGetSymbolAddress((void**)&part, g_part);
    cudaGetSymbolAddress((void**)&Mhi,  g_Mhi);
    cudaGetSymbolAddress((void**)&dvec, g_dvec);

    float* dec = (float*)d_out;
    float* z   = (float*)d_out + (size_t)NBATCH * IN_DIM;

    cudaFuncSetAttribute((const void*)gemm_fp16_kernel<8,2,1,4>,
                         cudaFuncAttributeMaxDynamicSharedMemorySize, SMEM_CFG(8,2,1,4));
    cudaFuncSetAttribute((const void*)gemm_fp16_kernel<8,1,1,4>,
                         cudaFuncAttributeMaxDynamicSharedMemorySize, SMEM_CFG(8,1,1,4));

    // 1. mask dtype probe
    detect_mask_kernel<<<1, 256>>>((const unsigned int*)W1m, 4096);

    // 2. fused prepass: split x | dequant W1 | dequant W2 (overlapped)
    prepass_kernel<<<NB_SPLIT + NB_DQ1 + NB_DQ2, 256>>>(
        (const float4*)x, xhi, xlo,
        W1i, W1m, W1f, cb1, W1hi, W1Thi,
        W2i, W2m, W2f, cb2, W2Thi);

    // 3. G1: z1 = c19(s1*(x @ Ŵ1) + b1)   2-product   [4096 x 8192], K=2048
    gemm_fp16_kernel<8,2,1,4><<<dim3(HDIM / 256, NBATCH / BM), 256, SMEM_CFG(8,2,1,4)>>>(
        xhi, xlo, W1Thi, nullptr, NBATCH, HDIM, IN_DIM, IN_DIM,
        cb1, nullptr, b1, 1, craw, rraw, nullptr, z1hi, nullptr);

    // 4. GM: M̂ partials (NI=8, K-split 4) -> part[0, 4M)   [2048 x 512], K=8192
    gemm_fp16_kernel<8,1,1,4><<<dim3(OUT_DIM / 256, IN_DIM / BM, 4), 256, SMEM_CFG(8,1,1,4)>>>(
        W1hi, nullptr, W2Thi, nullptr, IN_DIM, OUT_DIM, HDIM / 4, HDIM,
        nullptr, nullptr, nullptr, 0, nullptr, nullptr, part, nullptr, nullptr);

    // 5. G2: z1hi @ Ŵ2 partials (NI=8, K-split 4) -> part[4M, 12M)  [4096 x 512], K=8192
    gemm_fp16_kernel<8,1,1,4><<<dim3(OUT_DIM / 256, NBATCH / BM, 4), 256, SMEM_CFG(8,1,1,4)>>>(
        z1hi, nullptr, W2Thi, nullptr, NBATCH, OUT_DIM, HDIM / 4, HDIM,
        nullptr, nullptr, nullptr, 0, nullptr, nullptr, part + G2_PART_OFF, nullptr, nullptr);

    // 6. fused post: reduce M | dvec | reduce z (+ bias + fp16)
    postcombo_kernel<<<NB_RM + IN_DIM + NB_RZ, 256>>>(
        part, Mhi, W1hi, db1, db2, cb1, dvec, cb2, b2, z, zhi);

    // 7. G5: dec = s1*s2*(zhi @ M̂hiᵀ) + dvec  (NI=8, 1-product) [4096 x 2048], K=512
    gemm_fp16_kernel<8,1,1,4><<<dim3(IN_DIM / 256, NBATCH / BM), 256, SMEM_CFG(8,1,1,4)>>>(
        zhi, nullptr, Mhi, nullptr, NBATCH, IN_DIM, OUT_DIM, OUT_DIM,
        cb1, cb2, dvec, 0, nullptr, nullptr, dec, nullptr, nullptr);
}